// round 5
// baseline (speedup 1.0000x reference)
#include <cuda_runtime.h>

#define BB 64
#define NN 1024
#define KK 8     // 7 knn + self
#define F1 16
#define D1 64    // H1*C1 = 4*16
#define D2 128   // H2*C2 = 4*32

typedef unsigned long long ull;
typedef unsigned int u32;

// Scratch (allocation-free rule: __device__ globals)
__device__ float g_xl1[BB * NN * D1];
__device__ float g_xr1[BB * NN * D1];
__device__ float g_h1 [BB * NN * D1];
__device__ float g_xl2[BB * NN * D2];
__device__ float g_xr2[BB * NN * D2];
__device__ float g_h2 [BB * NN * D2];
__device__ int   g_idx[BB * NN * KK];

// Packed dual-fp32 FMA (sm_103a f32x2 pipe — ptxas never emits this from C++)
__device__ __forceinline__ ull fma2(ull a, ull b, ull c) {
    ull d;
    asm("fma.rn.f32x2 %0, %1, %2, %3;" : "=l"(d) : "l"(a), "l"(b), "l"(c));
    return d;
}
__device__ __forceinline__ ull bcast2(float v) {
    ull d;
    asm("mov.b64 %0, {%1, %1};" : "=l"(d) : "r"(__float_as_uint(v)));
    return d;
}
__device__ __forceinline__ float lo32(ull v) { return __uint_as_float((u32)v); }
__device__ __forceinline__ float hi32(ull v) { return __uint_as_float((u32)(v >> 32)); }

// ---------------------------------------------------------------------------
// GEMM body: out = x @ W + b, 128-row x DOUT tile per block, 256 threads
// as 16(tx: cols) x 16(ty: rows). Thread tile = 8 rows x CT cols with
// ROW-PAIR packed f32x2 accumulators: acc[p][c] = {out[r0+2p][c], out[r0+2p+1][c]}.
//  - x staged transposed (plain float): per k, 2x LDS.128 give 4 natural
//    {r,r+1} f32x2 pairs. No MOV packing.
//  - W staged DUPLICATED ({w,w} ull) and chunk-permuted (phys = j*16 + tx) so
//    each of the CTC LDS.128 per k reads 16 contiguous 16B chunks: 2-cyc floor.
// Inner loop per k: (2 + CTC) LDS.128 + 4*CT fma2, zero ALU movs.
// ---------------------------------------------------------------------------
template<int FIN, int DOUT>
__device__ __forceinline__ void gemm_body(
    char* smem, int tileIdx, int matIdx,
    const float* __restrict__ x,
    const float* __restrict__ Wa, const float* __restrict__ ba,
    const float* __restrict__ Wb, const float* __restrict__ bb,
    float* __restrict__ outa, float* __restrict__ outb)
{
    constexpr int CT  = DOUT / 16;   // cols per thread: 4 or 8
    constexpr int CTC = CT / 2;      // 16B W-chunks per thread per k: 2 or 4
    constexpr int RXf = 132;         // xs row stride (floats)

    float* xs = (float*)smem;                                  // FIN*RXf
    ull*   wd = (ull*)(smem + FIN * RXf * 4);                  // FIN*DOUT (dup)
    float* sb = (float*)(smem + FIN * RXf * 4 + FIN * DOUT * 8);

    const float* W    = matIdx ? Wb   : Wa;
    const float* bias = matIdx ? bb   : ba;
    float*       out  = matIdx ? outb : outa;

    int tid  = threadIdx.x;
    int base = tileIdx * 128;

    // Stage W duplicated + chunk-permuted: logical chunk q = c>>1 maps to
    // phys = (q % CTC)*16 + (q / CTC); ull slot = phys*2 + (c&1).
    for (int i = tid; i < FIN * DOUT; i += 256) {
        int k = i / DOUT, c = i - k * DOUT;
        int q = c >> 1;
        int phys = (q % CTC) * 16 + (q / CTC);
        wd[k * DOUT + phys * 2 + (c & 1)] = bcast2(W[i]);
    }
    if (tid < DOUT) sb[tid] = bias[tid];
    // Stage x tile transposed
    for (int i = tid; i < 128 * FIN; i += 256) {
        int r = i / FIN, k = i - r * FIN;
        xs[k * RXf + r] = x[(size_t)(base + r) * FIN + k];
    }
    __syncthreads();

    int tx = tid & 15, ty = tid >> 4;
    int r0 = ty * 8, c0 = tx * CT;

    ull acc[4][CT];
#pragma unroll
    for (int c = 0; c < CT; c++) {
        ull bv = bcast2(sb[c0 + c]);
#pragma unroll
        for (int p = 0; p < 4; p++) acc[p][c] = bv;
    }

#pragma unroll 4
    for (int k = 0; k < FIN; k++) {
        float4 xa = *(const float4*)(xs + k * RXf + r0);
        float4 xb = *(const float4*)(xs + k * RXf + r0 + 4);
        ull xp[4];
        xp[0] = ((const ull*)&xa)[0]; xp[1] = ((const ull*)&xa)[1];
        xp[2] = ((const ull*)&xb)[0]; xp[3] = ((const ull*)&xb)[1];

        ull wv[CT];
#pragma unroll
        for (int j = 0; j < CTC; j++) {
            ulonglong2 t = *(const ulonglong2*)(wd + k * DOUT + (j * 16 + tx) * 2);
            wv[2 * j] = t.x; wv[2 * j + 1] = t.y;
        }
#pragma unroll
        for (int p = 0; p < 4; p++)
#pragma unroll
            for (int c = 0; c < CT; c++)
                acc[p][c] = fma2(xp[p], wv[c], acc[p][c]);
    }

    // Epilogue: split row pairs and store vectorized
#pragma unroll
    for (int p = 0; p < 4; p++) {
        float* ro0 = out + (size_t)(base + r0 + 2 * p) * DOUT + c0;
        float* ro1 = ro0 + DOUT;
#pragma unroll
        for (int c4 = 0; c4 < CT / 4; c4++) {
            float4 v0, v1;
            v0.x = lo32(acc[p][4 * c4 + 0]); v1.x = hi32(acc[p][4 * c4 + 0]);
            v0.y = lo32(acc[p][4 * c4 + 1]); v1.y = hi32(acc[p][4 * c4 + 1]);
            v0.z = lo32(acc[p][4 * c4 + 2]); v1.z = hi32(acc[p][4 * c4 + 2]);
            v0.w = lo32(acc[p][4 * c4 + 3]); v1.w = hi32(acc[p][4 * c4 + 3]);
            ((float4*)ro0)[c4] = v0;
            ((float4*)ro1)[c4] = v1;
        }
    }
}

// ---------------------------------------------------------------------------
// KNN body: one (batch, 256-node chunk) per block.
// ---------------------------------------------------------------------------
__device__ __forceinline__ void knn_body(char* smem, int kb,
                                         const float* __restrict__ pos)
{
    float4* sp = (float4*)smem;
    int b = kb >> 2;
    const float* p = pos + (size_t)b * NN * 3;
    for (int i = threadIdx.x; i < NN; i += 256) {
        float x = p[i * 3 + 0], y = p[i * 3 + 1], z = p[i * 3 + 2];
        sp[i] = make_float4(x, y, z, x * x + y * y + z * z);
    }
    __syncthreads();

    int n = (kb & 3) * 256 + threadIdx.x;  // node 0..1023
    float4 me = sp[n];

    float bd[7];
    int   bi[7];
#pragma unroll
    for (int j = 0; j < 7; j++) { bd[j] = 3.4028235e38f; bi[j] = 0; }

#pragma unroll 2
    for (int m = 0; m < NN; m++) {
        float4 q = sp[m];
        float d = me.w + q.w - 2.f * (me.x * q.x + me.y * q.y + me.z * q.z);
        if (m != n && d < bd[6]) {
            bd[6] = d; bi[6] = m;
#pragma unroll
            for (int j = 6; j > 0; j--) {
                if (bd[j] < bd[j - 1]) {   // strict: ties keep earlier index first
                    float td = bd[j]; bd[j] = bd[j - 1]; bd[j - 1] = td;
                    int   ti = bi[j]; bi[j] = bi[j - 1]; bi[j - 1] = ti;
                }
            }
        }
    }

    int* o = g_idx + ((size_t)((b << 10) + n)) * KK;
#pragma unroll
    for (int j = 0; j < 7; j++) o[j] = bi[j];
    o[7] = n;  // self loop appended last, like the reference
}

// ---------------------------------------------------------------------------
// Stage 1: blocks [0,1024) = layer-1 GEMM (bit 9 selects Wl/Wr),
//          blocks [1024,1280) = KNN. Both only feed attn1 -> safe to fuse.
// ---------------------------------------------------------------------------
__global__ void __launch_bounds__(256) stage1_kernel(
    const float* __restrict__ pos, const float* __restrict__ x,
    const float* __restrict__ Wl1, const float* __restrict__ bl1,
    const float* __restrict__ Wr1, const float* __restrict__ br1,
    float* __restrict__ xl1, float* __restrict__ xr1)
{
    __shared__ __align__(16) char smem[17024];
    if (blockIdx.x < 1024) {
        gemm_body<F1, D1>(smem, blockIdx.x & 511, blockIdx.x >> 9,
                          x, Wl1, bl1, Wr1, br1, xl1, xr1);
    } else {
        knn_body(smem, blockIdx.x - 1024, pos);
    }
}

// ---------------------------------------------------------------------------
// Layer-2 GEMM kernel (grid.y picks Wl/Wr).
// ---------------------------------------------------------------------------
__global__ void __launch_bounds__(256) gemm2_kernel(
    const float* __restrict__ x,
    const float* __restrict__ Wa, const float* __restrict__ ba,
    const float* __restrict__ Wb, const float* __restrict__ bb,
    float* __restrict__ outa, float* __restrict__ outb)
{
    __shared__ __align__(16) char smem[99840];  // xs 33792 + wd 65536 + sb 512
    gemm_body<D1, D2>(smem, blockIdx.x, blockIdx.y,
                      x, Wa, ba, Wb, bb, outa, outb);
}

// ---------------------------------------------------------------------------
// GATv2 attention + aggregation, one warp per node; vectorized loads/stores.
// ---------------------------------------------------------------------------
template<int C, int DOUT>
__global__ void attn_kernel(const float* __restrict__ xl, const float* __restrict__ xr,
                            const float* __restrict__ att, const float* __restrict__ bias,
                            float* __restrict__ out)
{
    constexpr int V = DOUT / 32;   // 2 or 4
    int node = (blockIdx.x * blockDim.x + threadIdx.x) >> 5;
    int lane = threadIdx.x & 31;
    int b = node >> 10;
    const int* nidx = g_idx + (size_t)node * KK;
    int4 i0 = *(const int4*)nidx;
    int4 i1 = *(const int4*)(nidx + 4);
    int srcs[KK] = {i0.x, i0.y, i0.z, i0.w, i1.x, i1.y, i1.z, i1.w};

    int c0 = lane * V;

    float xrv[V], attv[V];
    if constexpr (V == 4) {
        float4 t = *(const float4*)(xr + (size_t)node * DOUT + c0);
        xrv[0] = t.x; xrv[1] = t.y; xrv[2] = t.z; xrv[3] = t.w;
        float4 a = *(const float4*)(att + c0);
        attv[0] = a.x; attv[1] = a.y; attv[2] = a.z; attv[3] = a.w;
    } else {
        float2 t = *(const float2*)(xr + (size_t)node * DOUT + c0);
        xrv[0] = t.x; xrv[1] = t.y;
        float2 a = *(const float2*)(att + c0);
        attv[0] = a.x; attv[1] = a.y;
    }

    float xnb[KK][V];
    float lg[KK];
#pragma unroll
    for (int k = 0; k < KK; k++) {
        int src = (b << 10) + srcs[k];
        const float* pp = xl + (size_t)src * DOUT + c0;
        if constexpr (V == 4) {
            float4 t = *(const float4*)pp;
            xnb[k][0] = t.x; xnb[k][1] = t.y; xnb[k][2] = t.z; xnb[k][3] = t.w;
        } else {
            float2 t = *(const float2*)pp;
            xnb[k][0] = t.x; xnb[k][1] = t.y;
        }
        float s = 0.f;
#pragma unroll
        for (int v = 0; v < V; v++) {
            float e = xnb[k][v] + xrv[v];
            e = e > 0.f ? e : 0.2f * e;       // leaky_relu(0.2)
            s = fmaf(e, attv[v], s);
        }
        s += __shfl_xor_sync(0xffffffffu, s, 1);
        s += __shfl_xor_sync(0xffffffffu, s, 2);
        s += __shfl_xor_sync(0xffffffffu, s, 4);
        lg[k] = s;
    }

    float mx = lg[0];
#pragma unroll
    for (int k = 1; k < KK; k++) mx = fmaxf(mx, lg[k]);
    float ssum = 0.f;
#pragma unroll
    for (int k = 0; k < KK; k++) { lg[k] = __expf(lg[k] - mx); ssum += lg[k]; }
    float inv = 1.f / ssum;

    float o[V];
#pragma unroll
    for (int v = 0; v < V; v++) o[v] = 0.f;
#pragma unroll
    for (int k = 0; k < KK; k++) {
        float a = lg[k] * inv;
#pragma unroll
        for (int v = 0; v < V; v++) o[v] = fmaf(a, xnb[k][v], o[v]);
    }

    float* po = out + (size_t)node * DOUT + c0;
    if constexpr (V == 4) {
        float4 bv = *(const float4*)(bias + c0);
        float4 r;
        r.x = fmaxf(o[0] + bv.x, 0.f);
        r.y = fmaxf(o[1] + bv.y, 0.f);
        r.z = fmaxf(o[2] + bv.z, 0.f);
        r.w = fmaxf(o[3] + bv.w, 0.f);
        *(float4*)po = r;
    } else {
        float2 bv = *(const float2*)(bias + c0);
        float2 r;
        r.x = fmaxf(o[0] + bv.x, 0.f);
        r.y = fmaxf(o[1] + bv.y, 0.f);
        *(float2*)po = r;
    }
}

// ---------------------------------------------------------------------------
// Global mean pool over N. One block per batch; float4 per thread.
// ---------------------------------------------------------------------------
__global__ void pool_kernel(const float* __restrict__ h2, float* __restrict__ out)
{
    __shared__ float4 red[512];
    int b = blockIdx.x;
    int t = threadIdx.x;
    int c = t & 31;          // float4 column 0..31 (covers 128 floats)
    int s = t >> 5;          // stripe 0..15
    const float4* base = (const float4*)(h2 + (size_t)b * NN * D2);
    float4 acc = make_float4(0.f, 0.f, 0.f, 0.f);
#pragma unroll 4
    for (int n = s * (NN / 16); n < (s + 1) * (NN / 16); n++) {
        float4 v = base[n * 32 + c];
        acc.x += v.x; acc.y += v.y; acc.z += v.z; acc.w += v.w;
    }
    red[t] = acc;
    __syncthreads();
#pragma unroll
    for (int step = 256; step >= 32; step >>= 1) {
        if (t < step) {
            float4 o = red[t + step];
            float4 m = red[t];
            m.x += o.x; m.y += o.y; m.z += o.z; m.w += o.w;
            red[t] = m;
        }
        __syncthreads();
    }
    if (t < 32) {
        float4 m = red[t];
        const float inv = 1.f / (float)NN;
        ((float4*)(out + b * D2))[t] =
            make_float4(m.x * inv, m.y * inv, m.z * inv, m.w * inv);
    }
}

// ---------------------------------------------------------------------------
extern "C" void kernel_launch(void* const* d_in, const int* in_sizes, int n_in,
                              void* d_out, int out_size)
{
    const float* x     = (const float*)d_in[0];
    const float* pos   = (const float*)d_in[1];
    const float* Wl1   = (const float*)d_in[2];
    const float* bl1   = (const float*)d_in[3];
    const float* Wr1   = (const float*)d_in[4];
    const float* br1   = (const float*)d_in[5];
    const float* att1  = (const float*)d_in[6];
    const float* bias1 = (const float*)d_in[7];
    const float* Wl2   = (const float*)d_in[8];
    const float* bl2   = (const float*)d_in[9];
    const float* Wr2   = (const float*)d_in[10];
    const float* br2   = (const float*)d_in[11];
    const float* att2  = (const float*)d_in[12];
    const float* bias2 = (const float*)d_in[13];
    float* out = (float*)d_out;

    float *xl1, *xr1, *h1, *xl2, *xr2, *h2;
    cudaGetSymbolAddress((void**)&xl1, g_xl1);
    cudaGetSymbolAddress((void**)&xr1, g_xr1);
    cudaGetSymbolAddress((void**)&h1,  g_h1);
    cudaGetSymbolAddress((void**)&xl2, g_xl2);
    cudaGetSymbolAddress((void**)&xr2, g_xr2);
    cudaGetSymbolAddress((void**)&h2,  g_h2);

    // 1) KNN + layer-1 transforms fused (independent work, one launch)
    stage1_kernel<<<1280, 256>>>(pos, x, Wl1, bl1, Wr1, br1, xl1, xr1);

    // 2) Layer-1 attention + ReLU
    attn_kernel<16, D1><<<(BB * NN * 32) / 256, 256>>>(xl1, xr1, att1, bias1, h1);

    // 3) Layer-2 transforms
    gemm2_kernel<<<dim3(BB * NN / 128, 2), 256>>>(h1, Wl2, bl2, Wr2, br2, xl2, xr2);

    // 4) Layer-2 attention + ReLU
    attn_kernel<32, D2><<<(BB * NN * 32) / 256, 256>>>(xl2, xr2, att2, bias2, h2);

    // 5) Global mean pool
    pool_kernel<<<BB, 512>>>(h2, out);
}

// round 6
// speedup vs baseline: 1.1276x; 1.1276x over previous
#include <cuda_runtime.h>

#define BB 64
#define NN 1024
#define KK 8     // 7 knn + self
#define F1 16
#define D1 64    // H1*C1 = 4*16
#define D2 128   // H2*C2 = 4*32

typedef unsigned long long ull;
typedef unsigned int u32;

// Scratch (allocation-free rule: __device__ globals)
__device__ float g_xl1[BB * NN * D1];
__device__ float g_xr1[BB * NN * D1];
__device__ float g_h1 [BB * NN * D1];
__device__ float g_xl2[BB * NN * D2];
__device__ float g_xr2[BB * NN * D2];
__device__ float g_h2 [BB * NN * D2];
__device__ int   g_idx[BB * NN * KK];

// Packed dual-fp32 FMA (sm_103a f32x2 pipe — ptxas never emits this from C++)
__device__ __forceinline__ ull fma2(ull a, ull b, ull c) {
    ull d;
    asm("fma.rn.f32x2 %0, %1, %2, %3;" : "=l"(d) : "l"(a), "l"(b), "l"(c));
    return d;
}
__device__ __forceinline__ ull bcast2(float v) {
    ull d;
    asm("mov.b64 %0, {%1, %1};" : "=l"(d) : "r"(__float_as_uint(v)));
    return d;
}

// ---------------------------------------------------------------------------
// GEMM body (R4 structure + W chunk-permute): out = x @ W + b.
// Block tile 128 rows x DOUT, 256 threads = 16(tx: cols) x 16(ty: rows).
// Thread tile: 8 rows x CT cols, col-pair packed f32x2 accumulators.
// x staged transposed (plain float): 2 broadcast LDS.128 per k, lane-dup via
// mov.b64 on the ALU pipe. W staged chunk-PERMUTED (no duplication): the 16B
// chunk logically belonging to (tx, j) sits at phys chunk j*16+tx, so each of
// the CPT W LDS.128 per k reads 256B contiguous across lanes: 2 wavefronts
// instead of 4. Per k per warp: ~6 L1 wavefronts vs 8 fma2 issue cycles.
// ---------------------------------------------------------------------------
template<int FIN, int DOUT>
__device__ __forceinline__ void gemm_body(
    char* smem, int tileIdx, int matIdx,
    const float* __restrict__ x,
    const float* __restrict__ Wa, const float* __restrict__ ba,
    const float* __restrict__ Wb, const float* __restrict__ bb,
    float* __restrict__ outa, float* __restrict__ outb)
{
    constexpr int CT  = DOUT / 16;   // cols per thread (floats): 4 or 8
    constexpr int CU  = CT / 2;      // packed accumulators per row: 2 or 4
    constexpr int CPT = CT / 4;      // 16B W-chunks per thread per k: 1 or 2
    constexpr int RXf = 132;         // xs row stride (floats)

    float* xs = (float*)smem;                                   // FIN*RXf
    float* ws = (float*)(smem + FIN * RXf * 4);                 // FIN*DOUT (permuted)
    float* sb = (float*)(smem + FIN * RXf * 4 + FIN * DOUT * 4);

    const float* W    = matIdx ? Wb   : Wa;
    const float* bias = matIdx ? bb   : ba;
    float*       out  = matIdx ? outb : outa;

    int tid  = threadIdx.x;
    int base = tileIdx * 128;

    // Stage W chunk-permuted: element (k,c): chunk q=c>>2, owner tx=q/CPT,
    // sub-chunk j=q%CPT -> phys chunk j*16 + tx.
    for (int i = tid; i < FIN * DOUT; i += 256) {
        int k = i / DOUT, c = i - k * DOUT;
        int q = c >> 2;
        int phys = (q % CPT) * 16 + (q / CPT);
        ws[k * DOUT + phys * 4 + (c & 3)] = W[i];
    }
    if (tid < DOUT) sb[tid] = bias[tid];
    // Stage x tile transposed (coalesced LDG)
    for (int i = tid; i < 128 * FIN; i += 256) {
        int r = i / FIN, k = i - r * FIN;
        xs[k * RXf + r] = x[(size_t)(base + r) * FIN + k];
    }
    __syncthreads();

    int tx = tid & 15, ty = tid >> 4;
    int r0 = ty * 8, c0 = tx * CT;

    ull acc[8][CU];
    {
        const ull* bp = (const ull*)(sb + c0);
#pragma unroll
        for (int r = 0; r < 8; r++)
#pragma unroll
            for (int c = 0; c < CU; c++) acc[r][c] = bp[c];
    }

#pragma unroll 4
    for (int k = 0; k < FIN; k++) {
        const float4* xp = (const float4*)(xs + k * RXf + r0);
        float4 xa = xp[0], xb = xp[1];
        ull xv[8];
        xv[0] = bcast2(xa.x); xv[1] = bcast2(xa.y);
        xv[2] = bcast2(xa.z); xv[3] = bcast2(xa.w);
        xv[4] = bcast2(xb.x); xv[5] = bcast2(xb.y);
        xv[6] = bcast2(xb.z); xv[7] = bcast2(xb.w);

        ull wv[CU];
#pragma unroll
        for (int j = 0; j < CPT; j++) {
            ulonglong2 t = *(const ulonglong2*)(ws + k * DOUT + (j * 16 + tx) * 4);
            wv[2 * j] = t.x; wv[2 * j + 1] = t.y;
        }
#pragma unroll
        for (int r = 0; r < 8; r++)
#pragma unroll
            for (int c = 0; c < CU; c++)
                acc[r][c] = fma2(xv[r], wv[c], acc[r][c]);
    }

#pragma unroll
    for (int r = 0; r < 8; r++) {
        ulonglong2* op = (ulonglong2*)(out + (size_t)(base + r0 + r) * DOUT + c0);
#pragma unroll
        for (int c = 0; c < CU / 2; c++)
            op[c] = make_ulonglong2(acc[r][2 * c], acc[r][2 * c + 1]);
    }
}

// ---------------------------------------------------------------------------
// KNN body: one (batch, 256-node chunk) per block.
// ---------------------------------------------------------------------------
__device__ __forceinline__ void knn_body(char* smem, int kb,
                                         const float* __restrict__ pos)
{
    float4* sp = (float4*)smem;
    int b = kb >> 2;
    const float* p = pos + (size_t)b * NN * 3;
    for (int i = threadIdx.x; i < NN; i += 256) {
        float x = p[i * 3 + 0], y = p[i * 3 + 1], z = p[i * 3 + 2];
        sp[i] = make_float4(x, y, z, x * x + y * y + z * z);
    }
    __syncthreads();

    int n = (kb & 3) * 256 + threadIdx.x;  // node 0..1023
    float4 me = sp[n];

    float bd[7];
    int   bi[7];
#pragma unroll
    for (int j = 0; j < 7; j++) { bd[j] = 3.4028235e38f; bi[j] = 0; }

#pragma unroll 2
    for (int m = 0; m < NN; m++) {
        float4 q = sp[m];
        float d = me.w + q.w - 2.f * (me.x * q.x + me.y * q.y + me.z * q.z);
        if (m != n && d < bd[6]) {
            bd[6] = d; bi[6] = m;
#pragma unroll
            for (int j = 6; j > 0; j--) {
                if (bd[j] < bd[j - 1]) {   // strict: ties keep earlier index first
                    float td = bd[j]; bd[j] = bd[j - 1]; bd[j - 1] = td;
                    int   ti = bi[j]; bi[j] = bi[j - 1]; bi[j - 1] = ti;
                }
            }
        }
    }

    int* o = g_idx + ((size_t)((b << 10) + n)) * KK;
#pragma unroll
    for (int j = 0; j < 7; j++) o[j] = bi[j];
    o[7] = n;  // self loop appended last, like the reference
}

// ---------------------------------------------------------------------------
// Stage 1: blocks [0,1024) = layer-1 GEMM (bit 9 selects Wl/Wr),
//          blocks [1024,1280) = KNN. Both only feed attn1 -> safe to fuse.
// smem: gemm<16,64> needs 16*132*4 + 16*64*4 + 256 = 12800B; knn needs 16384B.
// ---------------------------------------------------------------------------
__global__ void __launch_bounds__(256) stage1_kernel(
    const float* __restrict__ pos, const float* __restrict__ x,
    const float* __restrict__ Wl1, const float* __restrict__ bl1,
    const float* __restrict__ Wr1, const float* __restrict__ br1,
    float* __restrict__ xl1, float* __restrict__ xr1)
{
    __shared__ __align__(16) char smem[16512];
    if (blockIdx.x < 1024) {
        gemm_body<F1, D1>(smem, blockIdx.x & 511, blockIdx.x >> 9,
                          x, Wl1, bl1, Wr1, br1, xl1, xr1);
    } else {
        knn_body(smem, blockIdx.x - 1024, pos);
    }
}

// ---------------------------------------------------------------------------
// Layer-2 GEMM kernel (grid.y picks Wl/Wr).
// smem: 64*132*4 + 64*128*4 + 512 = 67072B.
// ---------------------------------------------------------------------------
__global__ void __launch_bounds__(256) gemm2_kernel(
    const float* __restrict__ x,
    const float* __restrict__ Wa, const float* __restrict__ ba,
    const float* __restrict__ Wb, const float* __restrict__ bb,
    float* __restrict__ outa, float* __restrict__ outb)
{
    __shared__ __align__(16) char smem[67072];
    gemm_body<D1, D2>(smem, blockIdx.x, blockIdx.y,
                      x, Wa, ba, Wb, bb, outa, outb);
}

// ---------------------------------------------------------------------------
// GATv2 attention + aggregation, one warp per node; vectorized loads/stores.
// ---------------------------------------------------------------------------
template<int C, int DOUT>
__global__ void attn_kernel(const float* __restrict__ xl, const float* __restrict__ xr,
                            const float* __restrict__ att, const float* __restrict__ bias,
                            float* __restrict__ out)
{
    constexpr int V = DOUT / 32;   // 2 or 4
    int node = (blockIdx.x * blockDim.x + threadIdx.x) >> 5;
    int lane = threadIdx.x & 31;
    int b = node >> 10;
    const int* nidx = g_idx + (size_t)node * KK;
    int4 i0 = *(const int4*)nidx;
    int4 i1 = *(const int4*)(nidx + 4);
    int srcs[KK] = {i0.x, i0.y, i0.z, i0.w, i1.x, i1.y, i1.z, i1.w};

    int c0 = lane * V;

    float xrv[V], attv[V];
    if constexpr (V == 4) {
        float4 t = *(const float4*)(xr + (size_t)node * DOUT + c0);
        xrv[0] = t.x; xrv[1] = t.y; xrv[2] = t.z; xrv[3] = t.w;
        float4 a = *(const float4*)(att + c0);
        attv[0] = a.x; attv[1] = a.y; attv[2] = a.z; attv[3] = a.w;
    } else {
        float2 t = *(const float2*)(xr + (size_t)node * DOUT + c0);
        xrv[0] = t.x; xrv[1] = t.y;
        float2 a = *(const float2*)(att + c0);
        attv[0] = a.x; attv[1] = a.y;
    }

    float xnb[KK][V];
    float lg[KK];
#pragma unroll
    for (int k = 0; k < KK; k++) {
        int src = (b << 10) + srcs[k];
        const float* pp = xl + (size_t)src * DOUT + c0;
        if constexpr (V == 4) {
            float4 t = *(const float4*)pp;
            xnb[k][0] = t.x; xnb[k][1] = t.y; xnb[k][2] = t.z; xnb[k][3] = t.w;
        } else {
            float2 t = *(const float2*)pp;
            xnb[k][0] = t.x; xnb[k][1] = t.y;
        }
        float s = 0.f;
#pragma unroll
        for (int v = 0; v < V; v++) {
            float e = xnb[k][v] + xrv[v];
            e = e > 0.f ? e : 0.2f * e;       // leaky_relu(0.2)
            s = fmaf(e, attv[v], s);
        }
        s += __shfl_xor_sync(0xffffffffu, s, 1);
        s += __shfl_xor_sync(0xffffffffu, s, 2);
        s += __shfl_xor_sync(0xffffffffu, s, 4);
        lg[k] = s;
    }

    float mx = lg[0];
#pragma unroll
    for (int k = 1; k < KK; k++) mx = fmaxf(mx, lg[k]);
    float ssum = 0.f;
#pragma unroll
    for (int k = 0; k < KK; k++) { lg[k] = __expf(lg[k] - mx); ssum += lg[k]; }
    float inv = 1.f / ssum;

    float o[V];
#pragma unroll
    for (int v = 0; v < V; v++) o[v] = 0.f;
#pragma unroll
    for (int k = 0; k < KK; k++) {
        float a = lg[k] * inv;
#pragma unroll
        for (int v = 0; v < V; v++) o[v] = fmaf(a, xnb[k][v], o[v]);
    }

    float* po = out + (size_t)node * DOUT + c0;
    if constexpr (V == 4) {
        float4 bv = *(const float4*)(bias + c0);
        float4 r;
        r.x = fmaxf(o[0] + bv.x, 0.f);
        r.y = fmaxf(o[1] + bv.y, 0.f);
        r.z = fmaxf(o[2] + bv.z, 0.f);
        r.w = fmaxf(o[3] + bv.w, 0.f);
        *(float4*)po = r;
    } else {
        float2 bv = *(const float2*)(bias + c0);
        float2 r;
        r.x = fmaxf(o[0] + bv.x, 0.f);
        r.y = fmaxf(o[1] + bv.y, 0.f);
        *(float2*)po = r;
    }
}

// ---------------------------------------------------------------------------
// Global mean pool over N. One block per batch; float4 per thread.
// ---------------------------------------------------------------------------
__global__ void pool_kernel(const float* __restrict__ h2, float* __restrict__ out)
{
    __shared__ float4 red[512];
    int b = blockIdx.x;
    int t = threadIdx.x;
    int c = t & 31;          // float4 column 0..31 (covers 128 floats)
    int s = t >> 5;          // stripe 0..15
    const float4* base = (const float4*)(h2 + (size_t)b * NN * D2);
    float4 acc = make_float4(0.f, 0.f, 0.f, 0.f);
#pragma unroll 4
    for (int n = s * (NN / 16); n < (s + 1) * (NN / 16); n++) {
        float4 v = base[n * 32 + c];
        acc.x += v.x; acc.y += v.y; acc.z += v.z; acc.w += v.w;
    }
    red[t] = acc;
    __syncthreads();
#pragma unroll
    for (int step = 256; step >= 32; step >>= 1) {
        if (t < step) {
            float4 o = red[t + step];
            float4 m = red[t];
            m.x += o.x; m.y += o.y; m.z += o.z; m.w += o.w;
            red[t] = m;
        }
        __syncthreads();
    }
    if (t < 32) {
        float4 m = red[t];
        const float inv = 1.f / (float)NN;
        ((float4*)(out + b * D2))[t] =
            make_float4(m.x * inv, m.y * inv, m.z * inv, m.w * inv);
    }
}

// ---------------------------------------------------------------------------
extern "C" void kernel_launch(void* const* d_in, const int* in_sizes, int n_in,
                              void* d_out, int out_size)
{
    const float* x     = (const float*)d_in[0];
    const float* pos   = (const float*)d_in[1];
    const float* Wl1   = (const float*)d_in[2];
    const float* bl1   = (const float*)d_in[3];
    const float* Wr1   = (const float*)d_in[4];
    const float* br1   = (const float*)d_in[5];
    const float* att1  = (const float*)d_in[6];
    const float* bias1 = (const float*)d_in[7];
    const float* Wl2   = (const float*)d_in[8];
    const float* bl2   = (const float*)d_in[9];
    const float* Wr2   = (const float*)d_in[10];
    const float* br2   = (const float*)d_in[11];
    const float* att2  = (const float*)d_in[12];
    const float* bias2 = (const float*)d_in[13];
    float* out = (float*)d_out;

    float *xl1, *xr1, *h1, *xl2, *xr2, *h2;
    cudaGetSymbolAddress((void**)&xl1, g_xl1);
    cudaGetSymbolAddress((void**)&xr1, g_xr1);
    cudaGetSymbolAddress((void**)&h1,  g_h1);
    cudaGetSymbolAddress((void**)&xl2, g_xl2);
    cudaGetSymbolAddress((void**)&xr2, g_xr2);
    cudaGetSymbolAddress((void**)&h2,  g_h2);

    // 1) KNN + layer-1 transforms fused (independent work, one launch)
    stage1_kernel<<<1280, 256>>>(pos, x, Wl1, bl1, Wr1, br1, xl1, xr1);

    // 2) Layer-1 attention + ReLU
    attn_kernel<16, D1><<<(BB * NN * 32) / 256, 256>>>(xl1, xr1, att1, bias1, h1);

    // 3) Layer-2 transforms
    gemm2_kernel<<<dim3(BB * NN / 128, 2), 256>>>(h1, Wl2, bl2, Wr2, br2, xl2, xr2);

    // 4) Layer-2 attention + ReLU
    attn_kernel<32, D2><<<(BB * NN * 32) / 256, 256>>>(xl2, xr2, att2, bias2, h2);

    // 5) Global mean pool
    pool_kernel<<<BB, 512>>>(h2, out);
}

// round 7
// speedup vs baseline: 1.3838x; 1.2272x over previous
#include <cuda_runtime.h>

#define BB 64
#define NN 1024
#define KK 8     // 7 knn + self
#define F1 16
#define D1 64    // H1*C1 = 4*16
#define D2 128   // H2*C2 = 4*32

typedef unsigned long long ull;
typedef unsigned int u32;

// Scratch (allocation-free rule: __device__ globals)
__device__ float g_xl1[BB * NN * D1];
__device__ float g_xr1[BB * NN * D1];
__device__ float g_h1 [BB * NN * D1];
__device__ float g_xl2[BB * NN * D2];
__device__ float g_xr2[BB * NN * D2];
__device__ float g_part[BB * (NN / 8) * D2];   // attn2+pool partials (4MB)
__device__ int   g_idx[BB * NN * KK];

// Packed dual-fp32 FMA (sm_103a f32x2 pipe — ptxas never emits this from C++)
__device__ __forceinline__ ull fma2(ull a, ull b, ull c) {
    ull d;
    asm("fma.rn.f32x2 %0, %1, %2, %3;" : "=l"(d) : "l"(a), "l"(b), "l"(c));
    return d;
}
__device__ __forceinline__ ull bcast2(float v) {
    ull d;
    asm("mov.b64 %0, {%1, %1};" : "=l"(d) : "r"(__float_as_uint(v)));
    return d;
}

// ---------------------------------------------------------------------------
// KNN: one batch per blockIdx.y, 256 threads/block, 4 blocks in x cover N=1024.
// ---------------------------------------------------------------------------
__global__ void knn_kernel(const float* __restrict__ pos)
{
    __shared__ float4 sp[NN];
    int b = blockIdx.y;
    const float* p = pos + (size_t)b * NN * 3;
    for (int i = threadIdx.x; i < NN; i += blockDim.x) {
        float x = p[i * 3 + 0], y = p[i * 3 + 1], z = p[i * 3 + 2];
        sp[i] = make_float4(x, y, z, x * x + y * y + z * z);
    }
    __syncthreads();

    int n = blockIdx.x * blockDim.x + threadIdx.x;  // node 0..1023
    float4 me = sp[n];

    float bd[7];
    int   bi[7];
#pragma unroll
    for (int j = 0; j < 7; j++) { bd[j] = 3.4028235e38f; bi[j] = 0; }

#pragma unroll 2
    for (int m = 0; m < NN; m++) {
        float4 q = sp[m];
        float d = me.w + q.w - 2.f * (me.x * q.x + me.y * q.y + me.z * q.z);
        if (m != n && d < bd[6]) {
            bd[6] = d; bi[6] = m;
#pragma unroll
            for (int j = 6; j > 0; j--) {
                if (bd[j] < bd[j - 1]) {   // strict: ties keep earlier index first
                    float td = bd[j]; bd[j] = bd[j - 1]; bd[j - 1] = td;
                    int   ti = bi[j]; bi[j] = bi[j - 1]; bi[j - 1] = ti;
                }
            }
        }
    }

    int* o = g_idx + ((size_t)((b << 10) + n)) * KK;
#pragma unroll
    for (int j = 0; j < 7; j++) o[j] = bi[j];
    o[7] = n;  // self loop appended last, like the reference
}

// ---------------------------------------------------------------------------
// Register-blocked GEMM (R4 structure + W chunk-permute): out = x @ W + b.
// grid.y picks Wl/Wr. Block tile 128 rows x DOUT, 256 threads = 16x16.
// Thread tile: 8 rows x CT cols, col-pair packed f32x2 accumulators.
// x staged transposed; per k: 2 broadcast LDS.128 (1 wavefront each) + lane
// duplication via mov.b64 (ALU pipe, overlaps FMA).
// W staged chunk-PERMUTED: the 16B chunk for (tx, j) sits at phys j*16+tx,
// so each W LDS.128 reads 256B contiguous across the 16 tx lanes: 2 wavefronts
// instead of 4. Per k per warp: ~6 L1 wavefronts < 8 fma2 issue cycles.
// ---------------------------------------------------------------------------
template<int FIN, int DOUT>
__global__ void __launch_bounds__(256) gemm_kernel(
    const float* __restrict__ x,
    const float* __restrict__ Wa, const float* __restrict__ ba,
    const float* __restrict__ Wb, const float* __restrict__ bb,
    float* __restrict__ outa, float* __restrict__ outb)
{
    constexpr int CT  = DOUT / 16;           // cols per thread: 4 or 8
    constexpr int CU  = CT / 2;              // packed accumulators: 2 or 4
    constexpr int CPT = (CT / 4 > 0) ? CT / 4 : 1;  // W chunks per thread: 1 or 2
    constexpr int RXf = 132;                 // xs row stride (floats)

    __shared__ float xs[FIN * RXf];
    __shared__ float ws[FIN * DOUT];
    __shared__ float sb[DOUT];

    const float* W    = blockIdx.y ? Wb   : Wa;
    const float* bias = blockIdx.y ? bb   : ba;
    float*       out  = blockIdx.y ? outb : outa;

    int tid  = threadIdx.x;
    int base = blockIdx.x * 128;

    // Stage W chunk-permuted: element (k,c): chunk q=c>>2 -> phys (q%CPT)*16+q/CPT
    for (int i = tid; i < FIN * DOUT; i += 256) {
        int k = i / DOUT, c = i - k * DOUT;
        int q = c >> 2;
        int phys = (q % CPT) * 16 + (q / CPT);
        ws[k * DOUT + phys * 4 + (c & 3)] = W[i];
    }
    if (tid < DOUT) sb[tid] = bias[tid];
    // Stage x tile transposed (coalesced LDG)
    for (int i = tid; i < 128 * FIN; i += 256) {
        int r = i / FIN, k = i - r * FIN;
        xs[k * RXf + r] = x[(size_t)(base + r) * FIN + k];
    }
    __syncthreads();

    int tx = tid & 15, ty = tid >> 4;
    int r0 = ty * 8, c0 = tx * CT;

    ull acc[8][CU];
    {
        const ull* bp = (const ull*)(sb + c0);
#pragma unroll
        for (int r = 0; r < 8; r++)
#pragma unroll
            for (int c = 0; c < CU; c++) acc[r][c] = bp[c];
    }

#pragma unroll 4
    for (int k = 0; k < FIN; k++) {
        const float4* xp = (const float4*)(xs + k * RXf + r0);
        float4 xa = xp[0], xb = xp[1];
        ull xv[8];
        xv[0] = bcast2(xa.x); xv[1] = bcast2(xa.y);
        xv[2] = bcast2(xa.z); xv[3] = bcast2(xa.w);
        xv[4] = bcast2(xb.x); xv[5] = bcast2(xb.y);
        xv[6] = bcast2(xb.z); xv[7] = bcast2(xb.w);

        ull wv[CU];
#pragma unroll
        for (int j = 0; j < CPT; j++) {
            ulonglong2 t = *(const ulonglong2*)(ws + k * DOUT + (j * 16 + tx) * 4);
            wv[2 * j] = t.x; wv[2 * j + 1] = t.y;
        }
#pragma unroll
        for (int r = 0; r < 8; r++)
#pragma unroll
            for (int c = 0; c < CU; c++)
                acc[r][c] = fma2(xv[r], wv[c], acc[r][c]);
    }

#pragma unroll
    for (int r = 0; r < 8; r++) {
        ulonglong2* op = (ulonglong2*)(out + (size_t)(base + r0 + r) * DOUT + c0);
#pragma unroll
        for (int c = 0; c < CU / 2; c++)
            op[c] = make_ulonglong2(acc[r][2 * c], acc[r][2 * c + 1]);
    }
}

// ---------------------------------------------------------------------------
// GATv2 attention + aggregation for layer 1, one warp per node (R4 version).
// ---------------------------------------------------------------------------
__global__ void attn1_kernel(const float* __restrict__ xl, const float* __restrict__ xr,
                             const float* __restrict__ att, const float* __restrict__ bias,
                             float* __restrict__ out)
{
    constexpr int DOUT = D1, V = 2;
    int node = (blockIdx.x * blockDim.x + threadIdx.x) >> 5;
    int lane = threadIdx.x & 31;
    int b = node >> 10;
    const int* nidx = g_idx + (size_t)node * KK;
    int4 i0 = *(const int4*)nidx;
    int4 i1 = *(const int4*)(nidx + 4);
    int srcs[KK] = {i0.x, i0.y, i0.z, i0.w, i1.x, i1.y, i1.z, i1.w};

    int c0 = lane * V;

    float2 tr = *(const float2*)(xr + (size_t)node * DOUT + c0);
    float xrv[V] = {tr.x, tr.y};
    float2 ta = *(const float2*)(att + c0);
    float attv[V] = {ta.x, ta.y};

    float xnb[KK][V];
    float lg[KK];
#pragma unroll
    for (int k = 0; k < KK; k++) {
        int src = (b << 10) + srcs[k];
        float2 t = *(const float2*)(xl + (size_t)src * DOUT + c0);
        xnb[k][0] = t.x; xnb[k][1] = t.y;
        float s = 0.f;
#pragma unroll
        for (int v = 0; v < V; v++) {
            float e = xnb[k][v] + xrv[v];
            e = e > 0.f ? e : 0.2f * e;       // leaky_relu(0.2)
            s = fmaf(e, attv[v], s);
        }
        s += __shfl_xor_sync(0xffffffffu, s, 1);
        s += __shfl_xor_sync(0xffffffffu, s, 2);
        s += __shfl_xor_sync(0xffffffffu, s, 4);
        lg[k] = s;
    }

    float mx = lg[0];
#pragma unroll
    for (int k = 1; k < KK; k++) mx = fmaxf(mx, lg[k]);
    float ssum = 0.f;
#pragma unroll
    for (int k = 0; k < KK; k++) { lg[k] = __expf(lg[k] - mx); ssum += lg[k]; }
    float inv = 1.f / ssum;

    float o[V] = {0.f, 0.f};
#pragma unroll
    for (int k = 0; k < KK; k++) {
        float a = lg[k] * inv;
#pragma unroll
        for (int v = 0; v < V; v++) o[v] = fmaf(a, xnb[k][v], o[v]);
    }

    float2 bv = *(const float2*)(bias + c0);
    float2 r;
    r.x = fmaxf(o[0] + bv.x, 0.f);
    r.y = fmaxf(o[1] + bv.y, 0.f);
    *(float2*)(out + (size_t)node * DOUT + c0) = r;
}

// ---------------------------------------------------------------------------
// Layer-2 attention FUSED with partial mean-pool. 8 warps = 8 nodes per block
// (all in one batch). Per-node output (bias+ReLU) is reduced across the
// block's 8 nodes in smem; one 128-float partial per block goes to g_part.
// Saves the full h2 write (32MB) + pool read (32MB).
// ---------------------------------------------------------------------------
__global__ void __launch_bounds__(256) attn2_pool_kernel(
    const float* __restrict__ xl, const float* __restrict__ xr,
    const float* __restrict__ att, const float* __restrict__ bias,
    float* __restrict__ part)
{
    constexpr int DOUT = D2, V = 4;
    __shared__ float sacc[8 * D2];

    int warp = threadIdx.x >> 5;
    int lane = threadIdx.x & 31;
    int node = blockIdx.x * 8 + warp;
    int b = node >> 10;
    const int* nidx = g_idx + (size_t)node * KK;
    int4 i0 = *(const int4*)nidx;
    int4 i1 = *(const int4*)(nidx + 4);
    int srcs[KK] = {i0.x, i0.y, i0.z, i0.w, i1.x, i1.y, i1.z, i1.w};

    int c0 = lane * V;

    float4 tr = *(const float4*)(xr + (size_t)node * DOUT + c0);
    float xrv[V] = {tr.x, tr.y, tr.z, tr.w};
    float4 ta = *(const float4*)(att + c0);
    float attv[V] = {ta.x, ta.y, ta.z, ta.w};

    float xnb[KK][V];
    float lg[KK];
#pragma unroll
    for (int k = 0; k < KK; k++) {
        int src = (b << 10) + srcs[k];
        float4 t = *(const float4*)(xl + (size_t)src * DOUT + c0);
        xnb[k][0] = t.x; xnb[k][1] = t.y; xnb[k][2] = t.z; xnb[k][3] = t.w;
        float s = 0.f;
#pragma unroll
        for (int v = 0; v < V; v++) {
            float e = xnb[k][v] + xrv[v];
            e = e > 0.f ? e : 0.2f * e;       // leaky_relu(0.2)
            s = fmaf(e, attv[v], s);
        }
        s += __shfl_xor_sync(0xffffffffu, s, 1);
        s += __shfl_xor_sync(0xffffffffu, s, 2);
        s += __shfl_xor_sync(0xffffffffu, s, 4);
        lg[k] = s;
    }

    float mx = lg[0];
#pragma unroll
    for (int k = 1; k < KK; k++) mx = fmaxf(mx, lg[k]);
    float ssum = 0.f;
#pragma unroll
    for (int k = 0; k < KK; k++) { lg[k] = __expf(lg[k] - mx); ssum += lg[k]; }
    float inv = 1.f / ssum;

    float o[V] = {0.f, 0.f, 0.f, 0.f};
#pragma unroll
    for (int k = 0; k < KK; k++) {
        float a = lg[k] * inv;
#pragma unroll
        for (int v = 0; v < V; v++) o[v] = fmaf(a, xnb[k][v], o[v]);
    }

    float4 bv = *(const float4*)(bias + c0);
    float4 r;
    r.x = fmaxf(o[0] + bv.x, 0.f);
    r.y = fmaxf(o[1] + bv.y, 0.f);
    r.z = fmaxf(o[2] + bv.z, 0.f);
    r.w = fmaxf(o[3] + bv.w, 0.f);
    *(float4*)(sacc + warp * D2 + c0) = r;
    __syncthreads();

    int t = threadIdx.x;
    if (t < D2) {
        float s = 0.f;
#pragma unroll
        for (int w = 0; w < 8; w++) s += sacc[w * D2 + t];
        part[(size_t)blockIdx.x * D2 + t] = s;
    }
}

// ---------------------------------------------------------------------------
// Final pool reduce: out[b][c] = (1/N) * sum over 128 block-partials.
// ---------------------------------------------------------------------------
__global__ void pool_reduce_kernel(const float* __restrict__ part,
                                   float* __restrict__ out)
{
    int b = blockIdx.x, t = threadIdx.x;  // 128 threads
    const float* p = part + (size_t)b * (NN / 8) * D2 + t;
    float s = 0.f;
#pragma unroll 8
    for (int j = 0; j < NN / 8; j++) s += p[(size_t)j * D2];
    out[b * D2 + t] = s * (1.f / (float)NN);
}

// ---------------------------------------------------------------------------
extern "C" void kernel_launch(void* const* d_in, const int* in_sizes, int n_in,
                              void* d_out, int out_size)
{
    const float* x     = (const float*)d_in[0];
    const float* pos   = (const float*)d_in[1];
    const float* Wl1   = (const float*)d_in[2];
    const float* bl1   = (const float*)d_in[3];
    const float* Wr1   = (const float*)d_in[4];
    const float* br1   = (const float*)d_in[5];
    const float* att1  = (const float*)d_in[6];
    const float* bias1 = (const float*)d_in[7];
    const float* Wl2   = (const float*)d_in[8];
    const float* bl2   = (const float*)d_in[9];
    const float* Wr2   = (const float*)d_in[10];
    const float* br2   = (const float*)d_in[11];
    const float* att2  = (const float*)d_in[12];
    const float* bias2 = (const float*)d_in[13];
    float* out = (float*)d_out;

    float *xl1, *xr1, *h1, *xl2, *xr2, *part;
    cudaGetSymbolAddress((void**)&xl1,  g_xl1);
    cudaGetSymbolAddress((void**)&xr1,  g_xr1);
    cudaGetSymbolAddress((void**)&h1,   g_h1);
    cudaGetSymbolAddress((void**)&xl2,  g_xl2);
    cudaGetSymbolAddress((void**)&xr2,  g_xr2);
    cudaGetSymbolAddress((void**)&part, g_part);

    // 1) KNN graph
    knn_kernel<<<dim3(NN / 256, BB), 256>>>(pos);

    // 2) Layer-1 transforms (grid.y picks Wl/Wr), attention, ReLU
    gemm_kernel<F1, D1><<<dim3(BB * NN / 128, 2), 256>>>(
        x, Wl1, bl1, Wr1, br1, xl1, xr1);
    attn1_kernel<<<(BB * NN * 32) / 256, 256>>>(xl1, xr1, att1, bias1, h1);

    // 3) Layer-2 transforms
    gemm_kernel<D1, D2><<<dim3(BB * NN / 128, 2), 256>>>(
        h1, Wl2, bl2, Wr2, br2, xl2, xr2);

    // 4) Layer-2 attention + ReLU fused with partial mean pool
    attn2_pool_kernel<<<BB * NN / 8, 256>>>(xl2, xr2, att2, bias2, part);

    // 5) Final pool reduction
    pool_reduce_kernel<<<BB, 128>>>(part, out);
}